// round 7
// baseline (speedup 1.0000x reference)
#include <cuda_runtime.h>
#include <cuda_bf16.h>
#include <cooperative_groups.h>

namespace cg = cooperative_groups;

#define NBINS   2200
#define NCHAN   12
#define NBATCH  32
#define PLANE   65536            // 256*256
#define THREADS 256
#define N4PLANE (PLANE / 4)      // 16384 float4 per plane
#define HALF4   (N4PLANE / 2)    // 8192 float4 per CTA (2 CTAs per plane)

// out = hist_counts (init before atomics; out is poisoned by harness)
__global__ void init_out_kernel(const float4* __restrict__ hist_in,
                                float4* __restrict__ out) {
    int i = blockIdx.x * blockDim.x + threadIdx.x;
    if (i < (NCHAN * NBINS) / 4) out[i] = hist_in[i];
}

__device__ __forceinline__ void bin1(float f, int* sh) {
    if (f >= -1200.0f && f <= 1000.0f) {
        int idx = __float2int_rd(f + 1200.0f);
        atomicAdd(&sh[min(idx, NBINS - 1)], 1);
    }
}

__device__ __forceinline__ void bin4(float4 v, int* sh) {
    bin1(v.x, sh); bin1(v.y, sh); bin1(v.z, sh); bin1(v.w, sh);
}

// grid = NBATCH*NCHAN*2 = 768, cluster of 2 CTAs covering one (batch,channel)
// plane. Rank 1 merges its histogram into rank 0's over DSMEM; both CTAs
// then flush half of the merged histogram to global with float REDs.
__global__ __launch_bounds__(THREADS) __cluster_dims__(2, 1, 1)
void hist_kernel(const float* __restrict__ x, float* __restrict__ out) {
    __shared__ int sh[NBINS];
    for (int i = threadIdx.x; i < NBINS; i += THREADS) sh[i] = 0;
    __syncthreads();

    cg::cluster_group cl = cg::this_cluster();
    const int rank  = (int)cl.block_rank();     // 0 or 1
    const int plane = blockIdx.x >> 1;          // b * NCHAN + c  (B,C,H,W layout)
    const int chan  = plane % NCHAN;

    const float4* __restrict__ p = reinterpret_cast<const float4*>(x)
        + (size_t)plane * N4PLANE + (size_t)rank * HALF4;

    // 8192 float4 / 256 threads = 32 per thread; 4 front-batched cached
    // loads per iteration (MLP=4), 8 iterations.
    #pragma unroll
    for (int i = threadIdx.x; i < HALF4; i += 4 * THREADS) {
        float4 a = p[i];
        float4 b = p[i + THREADS];
        float4 c = p[i + 2 * THREADS];
        float4 d = p[i + 3 * THREADS];
        bin4(a, sh);
        bin4(b, sh);
        bin4(c, sh);
        bin4(d, sh);
    }

    cl.sync();   // both CTAs finished counting

    // Rank 1 merges its counts into rank 0's shared histogram via DSMEM.
    int* merged = cl.map_shared_rank(sh, 0);
    if (rank == 1) {
        for (int i = threadIdx.x; i < NBINS; i += THREADS) {
            int v = sh[i];
            if (v) atomicAdd(&merged[i], v);
        }
    }
    cl.sync();   // merge complete before anyone flushes

    // Flush merged histogram: rank0 takes bins [0,1100), rank1 [1100,2200),
    // reading the merged copy (rank1 over DSMEM). Exact float REDs.
    const int lo = rank * (NBINS / 2);
    const int hi = lo + (NBINS / 2);
    float* __restrict__ g = out + chan * NBINS;
    for (int i = lo + threadIdx.x; i < hi; i += THREADS) {
        int v = merged[i];
        if (v) atomicAdd(&g[i], (float)v);
    }

    cl.sync();   // rank0's SMEM must stay live until rank1 finishes reading
}

extern "C" void kernel_launch(void* const* d_in, const int* in_sizes, int n_in,
                              void* d_out, int out_size) {
    const float* x    = (const float*)d_in[0];       // [32,12,256,256] fp32
    const float* hist = (const float*)d_in[1];       // [12,2200] fp32
    float* out        = (float*)d_out;               // [12,2200] fp32

    const int n4 = (NCHAN * NBINS) / 4;              // 6600
    init_out_kernel<<<(n4 + 255) / 256, 256>>>((const float4*)hist, (float4*)out);
    hist_kernel<<<NBATCH * NCHAN * 2, THREADS>>>(x, out);
}